// round 4
// baseline (speedup 1.0000x reference)
#include <cuda_runtime.h>

// Problem constants
#define BB      512      // batch
#define INU     8        // in_units (k)
#define INCH    1152     // in_channels (i)
#define NU      10       // num_units (j)
#define US      16       // unit_size (u)
#define JU      160      // NU*US
#define KI      9216     // INU*INCH
#define BETA    1.45f
#define KSPLIT  64
#define KCHUNK  144      // KI/KSPLIT; divides INCH (1152 = 8*144), mult of 16
#define MT      64       // gemm M tile
#define BSPLIT  4        // gemm2 batch split
#define BCHUNK  (BB / BSPLIT)

// Scratch (device globals -- no allocation allowed)
__device__ float g_Wt[KI * JU];                 // Wt[k*INCH+i][ju] = W[i,j,u,k]
__device__ float g_Gpart[BSPLIT][KI * JU];      // batch-split partials of G = x^T @ v
__device__ float g_spart[KSPLIT * BB * JU];
__device__ float g_s[BB * JU];
__device__ float g_v[BB * JU];
__device__ float g_b[INCH * NU];
__device__ float g_c[INCH * NU];

// ---- packed fp32x2 helpers (Blackwell FFMA2) -------------------------------
__device__ __forceinline__ unsigned long long pk2(float v) {
    unsigned long long r;
    asm("mov.b64 %0, {%1, %1};" : "=l"(r) : "f"(v));
    return r;
}
__device__ __forceinline__ void ffma2(unsigned long long& d,
                                      unsigned long long a, unsigned long long b) {
    asm("fma.rn.f32x2 %0, %1, %2, %0;" : "+l"(d) : "l"(a), "l"(b));
}

// ---------------------------------------------------------------------------
__global__ void zero_b_k() {
    int idx = blockIdx.x * blockDim.x + threadIdx.x;
    if (idx < INCH * NU) g_b[idx] = 0.0f;
}

// Wt[(k*INCH+i)*JU + ju] = W[(i*JU+ju)*INU + k]
__global__ void transposeW_k(const float* __restrict__ W) {
    int idx = blockIdx.x * blockDim.x + threadIdx.x;   // over INCH*JU
    if (idx >= INCH * JU) return;
    int i = idx / JU;
    int ju = idx - i * JU;
    float4 w0 = *reinterpret_cast<const float4*>(&W[idx * 8]);
    float4 w1 = *reinterpret_cast<const float4*>(&W[idx * 8 + 4]);
    g_Wt[(0 * INCH + i) * JU + ju] = w0.x;
    g_Wt[(1 * INCH + i) * JU + ju] = w0.y;
    g_Wt[(2 * INCH + i) * JU + ju] = w0.z;
    g_Wt[(3 * INCH + i) * JU + ju] = w0.w;
    g_Wt[(4 * INCH + i) * JU + ju] = w1.x;
    g_Wt[(5 * INCH + i) * JU + ju] = w1.y;
    g_Wt[(6 * INCH + i) * JU + ju] = w1.z;
    g_Wt[(7 * INCH + i) * JU + ju] = w1.w;
}

// softmax over i (axis 0) for each column j of g_b (INCH x NU)
__global__ void softmax_k() {
    int j = blockIdx.x;
    __shared__ float red[128];
    int t = threadIdx.x;
    float mx = -1e30f;
    for (int i = t; i < INCH; i += 128) mx = fmaxf(mx, g_b[i * NU + j]);
    red[t] = mx; __syncthreads();
    for (int o = 64; o > 0; o >>= 1) {
        if (t < o) red[t] = fmaxf(red[t], red[t + o]);
        __syncthreads();
    }
    mx = red[0]; __syncthreads();
    float sum = 0.0f;
    for (int i = t; i < INCH; i += 128) sum += __expf(g_b[i * NU + j] - mx);
    red[t] = sum; __syncthreads();
    for (int o = 64; o > 0; o >>= 1) {
        if (t < o) red[t] += red[t + o];
        __syncthreads();
    }
    float inv = 1.0f / red[0];
    for (int i = t; i < INCH; i += 128)
        g_c[i * NU + j] = __expf(g_b[i * NU + j] - mx) * inv;
}

// ===========================================================================
// GEMM1: s_part = x(512 x 9216) @ (c ⊙ Wt)(9216 x 160), split-K, pipelined.
// Block tile 64(M) x 160(N), 256 threads, micro 4x10, FFMA2, double-buffer, occ 3.
__global__ __launch_bounds__(256, 3) void gemm1_k(const float* __restrict__ x) {
    __shared__ float As[2][16][MT];
    __shared__ float Bs[2][16][JU];
    const int m0 = blockIdx.x * MT;
    const int kbase0 = blockIdx.y * KCHUNK;
    const int i0 = kbase0 % INCH;                // chunk never crosses k-slice
    const int tid = threadIdx.x;
    const int trow = tid >> 4;                   // 0..15
    const int tcol = tid & 15;                   // 0..15
    const int nb = tcol * 10;
    const int j0 = nb >> 4;
    const int j1 = (nb + 9) >> 4;
    const int aRow = tid >> 2;                   // 0..63
    const int aCol = (tid & 3) * 4;              // 0,4,8,12
    const int bRow = tid >> 4;                   // 0..15

    unsigned long long acc[4][5];
#pragma unroll
    for (int r = 0; r < 4; r++)
#pragma unroll
        for (int c = 0; c < 5; c++) acc[r][c] = 0ULL;

    float4 rA;
    float2 rB[5];
    float rc0, rc1;

#define G1_FETCH(ks)                                                              \
    {                                                                             \
        rA = *reinterpret_cast<const float4*>(&x[(m0 + aRow) * KI + kbase0 + (ks) + aCol]); \
        const float* bp = &g_Wt[(kbase0 + (ks) + bRow) * JU + nb];                \
        rB[0] = *reinterpret_cast<const float2*>(bp + 0);                         \
        rB[1] = *reinterpret_cast<const float2*>(bp + 2);                         \
        rB[2] = *reinterpret_cast<const float2*>(bp + 4);                         \
        rB[3] = *reinterpret_cast<const float2*>(bp + 6);                         \
        rB[4] = *reinterpret_cast<const float2*>(bp + 8);                         \
        const float* cp = &g_c[(i0 + (ks) + bRow) * NU];                          \
        rc0 = cp[j0];                                                             \
        rc1 = cp[j1];                                                             \
    }

#define G1_STORE(buf)                                                             \
    {                                                                             \
        As[buf][aCol + 0][aRow] = rA.x;                                           \
        As[buf][aCol + 1][aRow] = rA.y;                                           \
        As[buf][aCol + 2][aRow] = rA.z;                                           \
        As[buf][aCol + 3][aRow] = rA.w;                                           \
        _Pragma("unroll")                                                         \
        for (int c = 0; c < 5; c++) {                                             \
            float2 w;                                                             \
            w.x = rB[c].x * (((nb + 2 * c) >> 4) == j0 ? rc0 : rc1);              \
            w.y = rB[c].y * (((nb + 2 * c + 1) >> 4) == j0 ? rc0 : rc1);          \
            *reinterpret_cast<float2*>(&Bs[buf][bRow][nb + 2 * c]) = w;           \
        }                                                                         \
    }

    G1_FETCH(0);
    G1_STORE(0);
    __syncthreads();

#pragma unroll 1
    for (int t = 0; t < KCHUNK / 16; t++) {
        const int buf = t & 1;
        if (t + 1 < KCHUNK / 16) G1_FETCH((t + 1) * 16);
#pragma unroll
        for (int kk = 0; kk < 16; kk++) {
            float4 a = *reinterpret_cast<const float4*>(&As[buf][kk][trow * 4]);
            unsigned long long ap[4];
            ap[0] = pk2(a.x); ap[1] = pk2(a.y); ap[2] = pk2(a.z); ap[3] = pk2(a.w);
#pragma unroll
            for (int c = 0; c < 5; c++) {
                unsigned long long bp =
                    *reinterpret_cast<const unsigned long long*>(&Bs[buf][kk][nb + 2 * c]);
#pragma unroll
                for (int r = 0; r < 4; r++) ffma2(acc[r][c], ap[r], bp);
            }
        }
        if (t + 1 < KCHUNK / 16) {
            G1_STORE(buf ^ 1);
            __syncthreads();
        }
    }

    float* out = &g_spart[blockIdx.y * (BB * JU)];
#pragma unroll
    for (int r = 0; r < 4; r++)
#pragma unroll
        for (int c = 0; c < 5; c++)
            *reinterpret_cast<unsigned long long*>(
                &out[(m0 + trow * 4 + r) * JU + nb + 2 * c]) = acc[r][c];
#undef G1_FETCH
#undef G1_STORE
}

// reduce split-K partials: s = sum over KSPLIT of s_part (float4, coalesced)
__global__ void reduceS_k() {
    int idx = blockIdx.x * blockDim.x + threadIdx.x;   // over BB*JU/4
    if (idx >= BB * JU / 4) return;
    float4 acc = make_float4(0.f, 0.f, 0.f, 0.f);
#pragma unroll 8
    for (int ks = 0; ks < KSPLIT; ks++) {
        float4 v = *reinterpret_cast<const float4*>(&g_spart[ks * (BB * JU) + idx * 4]);
        acc.x += v.x; acc.y += v.y; acc.z += v.z; acc.w += v.w;
    }
    *reinterpret_cast<float4*>(&g_s[idx * 4]) = acc;
}

// squash: mag_sq over j (num_units axis). Writes g_v, optionally also d_out.
__global__ void squash_k(float* __restrict__ out, int writeOut) {
    int idx = blockIdx.x * blockDim.x + threadIdx.x;   // (b,u): 512*16
    if (idx >= BB * US) return;
    int b = idx >> 4;
    int u = idx & 15;
    float sv[NU];
    float msq = 0.0f;
#pragma unroll
    for (int j = 0; j < NU; j++) {
        sv[j] = g_s[b * JU + j * US + u];
        msq += sv[j] * sv[j];
    }
    float mag = sqrtf(msq);
    float sc = msq / ((BETA + msq) * mag);
    if (writeOut) {
#pragma unroll
        for (int j = 0; j < NU; j++) out[b * JU + j * US + u] = sc * sv[j];
    } else {
#pragma unroll
        for (int j = 0; j < NU; j++) g_v[b * JU + j * US + u] = sc * sv[j];
    }
}

// ===========================================================================
// GEMM2: Gpart[s] = x^T chunk (9216 x BCHUNK) @ v chunk (BCHUNK x 160).
// Block tile 64(M over ki) x 160(N), 256 threads, micro 4x10, occ 3.
__global__ __launch_bounds__(256, 3) void gemm2_k(const float* __restrict__ x) {
    __shared__ float As[2][16][MT];
    __shared__ float Bs[2][16][JU];
    const int m0 = blockIdx.x * MT;            // over KI
    const int kb0 = blockIdx.y * BCHUNK;       // batch chunk
    const int tid = threadIdx.x;
    const int trow = tid >> 4;
    const int tcol = tid & 15;
    const int nb = tcol * 10;
    const int aK = tid >> 4;                   // 0..15
    const int aM = (tid & 15) * 4;
    const int bRow = tid >> 4;

    unsigned long long acc[4][5];
#pragma unroll
    for (int r = 0; r < 4; r++)
#pragma unroll
        for (int c = 0; c < 5; c++) acc[r][c] = 0ULL;

    float4 rA;
    float2 rB[5];

#define G2_FETCH(kb)                                                              \
    {                                                                             \
        rA = *reinterpret_cast<const float4*>(&x[((kb) + aK) * KI + m0 + aM]);    \
        const float* bp = &g_v[((kb) + bRow) * JU + nb];                          \
        rB[0] = *reinterpret_cast<const float2*>(bp + 0);                         \
        rB[1] = *reinterpret_cast<const float2*>(bp + 2);                         \
        rB[2] = *reinterpret_cast<const float2*>(bp + 4);                         \
        rB[3] = *reinterpret_cast<const float2*>(bp + 6);                         \
        rB[4] = *reinterpret_cast<const float2*>(bp + 8);                         \
    }

#define G2_STORE(buf)                                                             \
    {                                                                             \
        *reinterpret_cast<float4*>(&As[buf][aK][aM]) = rA;                        \
        _Pragma("unroll")                                                         \
        for (int c = 0; c < 5; c++)                                               \
            *reinterpret_cast<float2*>(&Bs[buf][bRow][nb + 2 * c]) = rB[c];       \
    }

    G2_FETCH(kb0);
    G2_STORE(0);
    __syncthreads();

#pragma unroll 1
    for (int t = 0; t < BCHUNK / 16; t++) {
        const int buf = t & 1;
        if (t + 1 < BCHUNK / 16) G2_FETCH(kb0 + (t + 1) * 16);
#pragma unroll
        for (int kk = 0; kk < 16; kk++) {
            float4 a = *reinterpret_cast<const float4*>(&As[buf][kk][trow * 4]);
            unsigned long long ap[4];
            ap[0] = pk2(a.x); ap[1] = pk2(a.y); ap[2] = pk2(a.z); ap[3] = pk2(a.w);
#pragma unroll
            for (int c = 0; c < 5; c++) {
                unsigned long long bp =
                    *reinterpret_cast<const unsigned long long*>(&Bs[buf][kk][nb + 2 * c]);
#pragma unroll
                for (int r = 0; r < 4; r++) ffma2(acc[r][c], ap[r], bp);
            }
        }
        if (t + 1 < BCHUNK / 16) {
            G2_STORE(buf ^ 1);
            __syncthreads();
        }
    }

    float* out = g_Gpart[blockIdx.y];
#pragma unroll
    for (int r = 0; r < 4; r++)
#pragma unroll
        for (int c = 0; c < 5; c++)
            *reinterpret_cast<unsigned long long*>(
                &out[(m0 + trow * 4 + r) * JU + nb + 2 * c]) = acc[r][c];
#undef G2_FETCH
#undef G2_STORE
}

// b[i,j] = (1/B) * sum_{k,u} Wt[(k*INCH+i)*JU + j*US+u] * (ΣGpart)[same]
__global__ void bupdate_k() {
    int gw = (blockIdx.x * blockDim.x + threadIdx.x) >> 5;
    int lane = threadIdx.x & 31;
    if (gw >= INCH * NU) return;
    int i = gw / NU;
    int j = gw - i * NU;
    int k = lane >> 2;
    int u = (lane & 3) * 4;
    int idx = (k * INCH + i) * JU + j * US + u;
    float4 w = *reinterpret_cast<const float4*>(&g_Wt[idx]);
    float4 g = *reinterpret_cast<const float4*>(&g_Gpart[0][idx]);
#pragma unroll
    for (int s = 1; s < BSPLIT; s++) {
        float4 gs = *reinterpret_cast<const float4*>(&g_Gpart[s][idx]);
        g.x += gs.x; g.y += gs.y; g.z += gs.z; g.w += gs.w;
    }
    float acc = w.x * g.x + w.y * g.y + w.z * g.z + w.w * g.w;
#pragma unroll
    for (int o = 16; o > 0; o >>= 1) acc += __shfl_xor_sync(0xffffffffu, acc, o);
    if (lane == 0) g_b[i * NU + j] = acc * (1.0f / (float)BB);
}

// ---------------------------------------------------------------------------
extern "C" void kernel_launch(void* const* d_in, const int* in_sizes, int n_in,
                              void* d_out, int out_size) {
    const float* x = (const float*)d_in[0];
    const float* W = (const float*)d_in[1];
    if (n_in >= 2 && in_sizes[0] == INCH * NU * US * INU) {
        const float* t = x; x = W; W = t;
    }
    float* out = (float*)d_out;

    zero_b_k<<<(INCH * NU + 255) / 256, 256>>>();
    transposeW_k<<<(INCH * JU + 255) / 256, 256>>>(W);

    for (int t = 0; t < 3; t++) {
        softmax_k<<<NU, 128>>>();
        gemm1_k<<<dim3(BB / MT, KSPLIT), 256>>>(x);
        reduceS_k<<<(BB * JU / 4 + 127) / 128, 128>>>();
        squash_k<<<(BB * US + 255) / 256, 256>>>(out, t == 2 ? 1 : 0);
        if (t < 2) {
            gemm2_k<<<dim3(KI / MT, BSPLIT), 256>>>(x);
            bupdate_k<<<(INCH * NU * 32) / 256, 256>>>();
        }
    }
}

// round 5
// speedup vs baseline: 1.8014x; 1.8014x over previous
#include <cuda_runtime.h>

// Problem constants
#define BB      512      // batch
#define INU     8        // in_units (k)
#define INCH    1152     // in_channels (i)
#define NU      10       // num_units (j)
#define US      16       // unit_size (u)
#define JU      160      // NU*US
#define KI      9216     // INU*INCH
#define BETA    1.45f
#define KSPLIT  72
#define KCHUNK  128      // KI / KSPLIT  (divides INCH: 1152 = 9*128)
#define MT      128      // gemm M tile
#define BSPLIT  4        // gemm2 batch split
#define BCHUNK  (BB / BSPLIT)

// Scratch (device globals -- no allocation allowed)
__device__ float g_Wt[KI * JU];                 // Wt[k*INCH+i][ju] = W[i,j,u,k]
__device__ float g_Gpart[BSPLIT][KI * JU];      // batch-split partials of G = x^T @ v
__device__ float g_spart[KSPLIT * BB * JU];
__device__ float g_s[BB * JU];
__device__ float g_v[BB * JU];
__device__ float g_b[INCH * NU];
__device__ float g_c[INCH * NU];

// ---- packed fp32x2 helpers (Blackwell FFMA2) -------------------------------
__device__ __forceinline__ unsigned long long pk2(float v) {
    unsigned long long r;
    asm("mov.b64 %0, {%1, %1};" : "=l"(r) : "f"(v));
    return r;
}
__device__ __forceinline__ void ffma2(unsigned long long& d,
                                      unsigned long long a, unsigned long long b) {
    asm("fma.rn.f32x2 %0, %1, %2, %0;" : "+l"(d) : "l"(a), "l"(b));
}

// ---------------------------------------------------------------------------
__global__ void zero_b_k() {
    int idx = blockIdx.x * blockDim.x + threadIdx.x;
    if (idx < INCH * NU) g_b[idx] = 0.0f;
}

// Wt[(k*INCH+i)*JU + ju] = W[(i*JU+ju)*INU + k]
__global__ void transposeW_k(const float* __restrict__ W) {
    int idx = blockIdx.x * blockDim.x + threadIdx.x;   // over INCH*JU
    if (idx >= INCH * JU) return;
    int i = idx / JU;
    int ju = idx - i * JU;
    float4 w0 = *reinterpret_cast<const float4*>(&W[idx * 8]);
    float4 w1 = *reinterpret_cast<const float4*>(&W[idx * 8 + 4]);
    g_Wt[(0 * INCH + i) * JU + ju] = w0.x;
    g_Wt[(1 * INCH + i) * JU + ju] = w0.y;
    g_Wt[(2 * INCH + i) * JU + ju] = w0.z;
    g_Wt[(3 * INCH + i) * JU + ju] = w0.w;
    g_Wt[(4 * INCH + i) * JU + ju] = w1.x;
    g_Wt[(5 * INCH + i) * JU + ju] = w1.y;
    g_Wt[(6 * INCH + i) * JU + ju] = w1.z;
    g_Wt[(7 * INCH + i) * JU + ju] = w1.w;
}

// softmax over i (axis 0) for each column j of g_b (INCH x NU)
__global__ void softmax_k() {
    int j = blockIdx.x;
    __shared__ float red[128];
    int t = threadIdx.x;
    float mx = -1e30f;
    for (int i = t; i < INCH; i += 128) mx = fmaxf(mx, g_b[i * NU + j]);
    red[t] = mx; __syncthreads();
    for (int o = 64; o > 0; o >>= 1) {
        if (t < o) red[t] = fmaxf(red[t], red[t + o]);
        __syncthreads();
    }
    mx = red[0]; __syncthreads();
    float sum = 0.0f;
    for (int i = t; i < INCH; i += 128) sum += __expf(g_b[i * NU + j] - mx);
    red[t] = sum; __syncthreads();
    for (int o = 64; o > 0; o >>= 1) {
        if (t < o) red[t] += red[t + o];
        __syncthreads();
    }
    float inv = 1.0f / red[0];
    for (int i = t; i < INCH; i += 128)
        g_c[i * NU + j] = __expf(g_b[i * NU + j] - mx) * inv;
}

// ===========================================================================
// GEMM1: s_part = x(512 x 9216) @ (c ⊙ Wt)(9216 x 160), split-K, pipelined.
// Block tile 128(M) x 160(N), 256 threads, micro 8x10, FFMA2, double-buffer.
__global__ __launch_bounds__(256, 2) void gemm1_k(const float* __restrict__ x) {
    __shared__ float As[2][16][MT];
    __shared__ float Bs[2][16][JU];
    const int m0 = blockIdx.x * MT;
    const int kbase0 = blockIdx.y * KCHUNK;
    const int i0 = kbase0 % INCH;                // chunk never crosses a k-slice
    const int tid = threadIdx.x;
    const int trow = tid >> 4;                   // 0..15
    const int tcol = tid & 15;                   // 0..15
    const int nb = tcol * 10;
    const int j0 = nb >> 4;
    const int j1 = (nb + 9) >> 4;
    const int aRow = tid >> 1;                   // 0..127
    const int aCol = (tid & 1) * 8;              // 0 or 8
    const int bRow = tid >> 4;                   // 0..15

    unsigned long long acc[8][5];
#pragma unroll
    for (int r = 0; r < 8; r++)
#pragma unroll
        for (int c = 0; c < 5; c++) acc[r][c] = 0ULL;

    float4 rA0, rA1;
    float2 rB[5];
    float rc0, rc1;

#define G1_FETCH(ks)                                                              \
    {                                                                             \
        const float* ap = &x[(m0 + aRow) * KI + kbase0 + (ks) + aCol];            \
        rA0 = *reinterpret_cast<const float4*>(ap);                               \
        rA1 = *reinterpret_cast<const float4*>(ap + 4);                           \
        const float* bp = &g_Wt[(kbase0 + (ks) + bRow) * JU + nb];                \
        rB[0] = *reinterpret_cast<const float2*>(bp + 0);                         \
        rB[1] = *reinterpret_cast<const float2*>(bp + 2);                         \
        rB[2] = *reinterpret_cast<const float2*>(bp + 4);                         \
        rB[3] = *reinterpret_cast<const float2*>(bp + 6);                         \
        rB[4] = *reinterpret_cast<const float2*>(bp + 8);                         \
        const float* cp = &g_c[(i0 + (ks) + bRow) * NU];                          \
        rc0 = cp[j0];                                                             \
        rc1 = cp[j1];                                                             \
    }

#define G1_STORE(buf)                                                             \
    {                                                                             \
        As[buf][aCol + 0][aRow] = rA0.x;                                          \
        As[buf][aCol + 1][aRow] = rA0.y;                                          \
        As[buf][aCol + 2][aRow] = rA0.z;                                          \
        As[buf][aCol + 3][aRow] = rA0.w;                                          \
        As[buf][aCol + 4][aRow] = rA1.x;                                          \
        As[buf][aCol + 5][aRow] = rA1.y;                                          \
        As[buf][aCol + 6][aRow] = rA1.z;                                          \
        As[buf][aCol + 7][aRow] = rA1.w;                                          \
        _Pragma("unroll")                                                         \
        for (int c = 0; c < 5; c++) {                                             \
            float2 w;                                                             \
            w.x = rB[c].x * (((nb + 2 * c) >> 4) == j0 ? rc0 : rc1);              \
            w.y = rB[c].y * (((nb + 2 * c + 1) >> 4) == j0 ? rc0 : rc1);          \
            *reinterpret_cast<float2*>(&Bs[buf][bRow][nb + 2 * c]) = w;           \
        }                                                                         \
    }

    G1_FETCH(0);
    G1_STORE(0);
    __syncthreads();

#pragma unroll 1
    for (int t = 0; t < KCHUNK / 16; t++) {
        const int buf = t & 1;
        if (t + 1 < KCHUNK / 16) G1_FETCH((t + 1) * 16);
#pragma unroll
        for (int kk = 0; kk < 16; kk++) {
            float4 a0 = *reinterpret_cast<const float4*>(&As[buf][kk][trow * 8]);
            float4 a1 = *reinterpret_cast<const float4*>(&As[buf][kk][trow * 8 + 4]);
            unsigned long long ap[8];
            ap[0] = pk2(a0.x); ap[1] = pk2(a0.y); ap[2] = pk2(a0.z); ap[3] = pk2(a0.w);
            ap[4] = pk2(a1.x); ap[5] = pk2(a1.y); ap[6] = pk2(a1.z); ap[7] = pk2(a1.w);
#pragma unroll
            for (int c = 0; c < 5; c++) {
                unsigned long long bp =
                    *reinterpret_cast<const unsigned long long*>(&Bs[buf][kk][nb + 2 * c]);
#pragma unroll
                for (int r = 0; r < 8; r++) ffma2(acc[r][c], ap[r], bp);
            }
        }
        if (t + 1 < KCHUNK / 16) {
            G1_STORE(buf ^ 1);
            __syncthreads();
        }
    }

    float* out = &g_spart[blockIdx.y * (BB * JU)];
#pragma unroll
    for (int r = 0; r < 8; r++)
#pragma unroll
        for (int c = 0; c < 5; c++)
            *reinterpret_cast<unsigned long long*>(
                &out[(m0 + trow * 8 + r) * JU + nb + 2 * c]) = acc[r][c];
#undef G1_FETCH
#undef G1_STORE
}

// reduce split-K partials: s = sum over KSPLIT of s_part (float4, coalesced)
__global__ void reduceS_k() {
    int idx = blockIdx.x * blockDim.x + threadIdx.x;   // over BB*JU/4
    if (idx >= BB * JU / 4) return;
    float4 acc = make_float4(0.f, 0.f, 0.f, 0.f);
#pragma unroll 8
    for (int ks = 0; ks < KSPLIT; ks++) {
        float4 v = *reinterpret_cast<const float4*>(&g_spart[ks * (BB * JU) + idx * 4]);
        acc.x += v.x; acc.y += v.y; acc.z += v.z; acc.w += v.w;
    }
    *reinterpret_cast<float4*>(&g_s[idx * 4]) = acc;
}

// squash: mag_sq over j (num_units axis). Writes g_v, optionally also d_out.
__global__ void squash_k(float* __restrict__ out, int writeOut) {
    int idx = blockIdx.x * blockDim.x + threadIdx.x;   // (b,u): 512*16
    if (idx >= BB * US) return;
    int b = idx >> 4;
    int u = idx & 15;
    float sv[NU];
    float msq = 0.0f;
#pragma unroll
    for (int j = 0; j < NU; j++) {
        sv[j] = g_s[b * JU + j * US + u];
        msq += sv[j] * sv[j];
    }
    float mag = sqrtf(msq);
    float sc = msq / ((BETA + msq) * mag);
    if (writeOut) {
#pragma unroll
        for (int j = 0; j < NU; j++) out[b * JU + j * US + u] = sc * sv[j];
    } else {
#pragma unroll
        for (int j = 0; j < NU; j++) g_v[b * JU + j * US + u] = sc * sv[j];
    }
}

// ===========================================================================
// GEMM2: Gpart[s] = x^T chunk (9216 x BCHUNK) @ v chunk (BCHUNK x 160), pipelined.
// Block tile 128(M over ki) x 160(N), 256 threads, micro 8x10, FFMA2.
__global__ __launch_bounds__(256, 2) void gemm2_k(const float* __restrict__ x) {
    __shared__ float As[2][16][MT];
    __shared__ float Bs[2][16][JU];
    const int m0 = blockIdx.x * MT;            // over KI
    const int kb0 = blockIdx.y * BCHUNK;       // batch chunk
    const int tid = threadIdx.x;
    const int trow = tid >> 4;
    const int tcol = tid & 15;
    const int nb = tcol * 10;
    const int aK = tid >> 5;                   // 0..7  (rows aK and aK+8)
    const int aM = (tid & 31) * 4;
    const int bRow = tid >> 4;

    unsigned long long acc[8][5];
#pragma unroll
    for (int r = 0; r < 8; r++)
#pragma unroll
        for (int c = 0; c < 5; c++) acc[r][c] = 0ULL;

    float4 rA0, rA1;
    float2 rB[5];

#define G2_FETCH(kb)                                                              \
    {                                                                             \
        rA0 = *reinterpret_cast<const float4*>(&x[((kb) + aK) * KI + m0 + aM]);   \
        rA1 = *reinterpret_cast<const float4*>(&x[((kb) + aK + 8) * KI + m0 + aM]);\
        const float* bp = &g_v[((kb) + bRow) * JU + nb];                          \
        rB[0] = *reinterpret_cast<const float2*>(bp + 0);                         \
        rB[1] = *reinterpret_cast<const float2*>(bp + 2);                         \
        rB[2] = *reinterpret_cast<const float2*>(bp + 4);                         \
        rB[3] = *reinterpret_cast<const float2*>(bp + 6);                         \
        rB[4] = *reinterpret_cast<const float2*>(bp + 8);                         \
    }

#define G2_STORE(buf)                                                             \
    {                                                                             \
        *reinterpret_cast<float4*>(&As[buf][aK][aM]) = rA0;                       \
        *reinterpret_cast<float4*>(&As[buf][aK + 8][aM]) = rA1;                   \
        _Pragma("unroll")                                                         \
        for (int c = 0; c < 5; c++)                                               \
            *reinterpret_cast<float2*>(&Bs[buf][bRow][nb + 2 * c]) = rB[c];       \
    }

    G2_FETCH(kb0);
    G2_STORE(0);
    __syncthreads();

#pragma unroll 1
    for (int t = 0; t < BCHUNK / 16; t++) {
        const int buf = t & 1;
        if (t + 1 < BCHUNK / 16) G2_FETCH(kb0 + (t + 1) * 16);
#pragma unroll
        for (int kk = 0; kk < 16; kk++) {
            float4 a0 = *reinterpret_cast<const float4*>(&As[buf][kk][trow * 8]);
            float4 a1 = *reinterpret_cast<const float4*>(&As[buf][kk][trow * 8 + 4]);
            unsigned long long ap[8];
            ap[0] = pk2(a0.x); ap[1] = pk2(a0.y); ap[2] = pk2(a0.z); ap[3] = pk2(a0.w);
            ap[4] = pk2(a1.x); ap[5] = pk2(a1.y); ap[6] = pk2(a1.z); ap[7] = pk2(a1.w);
#pragma unroll
            for (int c = 0; c < 5; c++) {
                unsigned long long bp =
                    *reinterpret_cast<const unsigned long long*>(&Bs[buf][kk][nb + 2 * c]);
#pragma unroll
                for (int r = 0; r < 8; r++) ffma2(acc[r][c], ap[r], bp);
            }
        }
        if (t + 1 < BCHUNK / 16) {
            G2_STORE(buf ^ 1);
            __syncthreads();
        }
    }

    float* out = g_Gpart[blockIdx.y];
#pragma unroll
    for (int r = 0; r < 8; r++)
#pragma unroll
        for (int c = 0; c < 5; c++)
            *reinterpret_cast<unsigned long long*>(
                &out[(m0 + trow * 8 + r) * JU + nb + 2 * c]) = acc[r][c];
#undef G2_FETCH
#undef G2_STORE
}

// b[i,j] = (1/B) * sum_{k,u} Wt[(k*INCH+i)*JU + j*US+u] * (ΣGpart)[same]
__global__ void bupdate_k() {
    int gw = (blockIdx.x * blockDim.x + threadIdx.x) >> 5;
    int lane = threadIdx.x & 31;
    if (gw >= INCH * NU) return;
    int i = gw / NU;
    int j = gw - i * NU;
    int k = lane >> 2;
    int u = (lane & 3) * 4;
    int idx = (k * INCH + i) * JU + j * US + u;
    float4 w = *reinterpret_cast<const float4*>(&g_Wt[idx]);
    float4 g = *reinterpret_cast<const float4*>(&g_Gpart[0][idx]);
#pragma unroll
    for (int s = 1; s < BSPLIT; s++) {
        float4 gs = *reinterpret_cast<const float4*>(&g_Gpart[s][idx]);
        g.x += gs.x; g.y += gs.y; g.z += gs.z; g.w += gs.w;
    }
    float acc = w.x * g.x + w.y * g.y + w.z * g.z + w.w * g.w;
#pragma unroll
    for (int o = 16; o > 0; o >>= 1) acc += __shfl_xor_sync(0xffffffffu, acc, o);
    if (lane == 0) g_b[i * NU + j] = acc * (1.0f / (float)BB);
}

// ---------------------------------------------------------------------------
extern "C" void kernel_launch(void* const* d_in, const int* in_sizes, int n_in,
                              void* d_out, int out_size) {
    const float* x = (const float*)d_in[0];
    const float* W = (const float*)d_in[1];
    if (n_in >= 2 && in_sizes[0] == INCH * NU * US * INU) {
        const float* t = x; x = W; W = t;
    }
    float* out = (float*)d_out;

    zero_b_k<<<(INCH * NU + 255) / 256, 256>>>();
    transposeW_k<<<(INCH * JU + 255) / 256, 256>>>(W);

    for (int t = 0; t < 3; t++) {
        softmax_k<<<NU, 128>>>();
        gemm1_k<<<dim3(BB / MT, KSPLIT), 256>>>(x);
        reduceS_k<<<(BB * JU / 4 + 127) / 128, 128>>>();
        squash_k<<<(BB * US + 255) / 256, 256>>>(out, t == 2 ? 1 : 0);
        if (t < 2) {
            gemm2_k<<<dim3(KI / MT, BSPLIT), 256>>>(x);
            bupdate_k<<<(INCH * NU * 32) / 256, 256>>>();
        }
    }
}